// round 14
// baseline (speedup 1.0000x reference)
#include <cuda_runtime.h>
#include <cstdint>

// CognitiveLorenzField, closed form, single fused kernel.
// a_t = ha[t]+Kq*ga[t], b_t = hb[t]+Kq*gb[t], c_t = cc[t]; tables + Lorenz z
// computed at compile time in double. Runtime = dot-product reduction (blocks
// 0..63) + pure streaming stores at the DRAM-write wall (~5.5 TB/s).
// R14: A/B the store cache-op — __stcg instead of __stcs — on the best-known
// R12 configuration (592 CTAs, 2 float4/thread, 8KB tiles, work stealing).

#define DIM       65536
#define STEPS     500
#define NSLICE    32                    // slices of 2048 floats (8KB)
#define TCHUNKS   50
#define CHUNK     10
#define NTILES    (TCHUNKS * NSLICE)    // 1600
#define NT        256
#define WRITERS   592                   // 4 CTA/SM, one wave
#define RBLK      64

struct Tabs {
    float ha[STEPS], ga[STEPS], hb[STEPS], gb[STEPS], cc[STEPS], zz[STEPS];
};

static constexpr Tabs make_tabs() {
    Tabs T{};
    double x = 1.0, y = 1.0, z = 1.0;
    double ha = 1.0, hb = 0.0, ga = 0.0, gb = 0.0, c = 1.0;
    const double dt = 0.01;
    for (int t = 0; t < STEPS; t++) {
        double dx = 10.0 * (y - x);
        double dy = x * (28.0 - z) - y;
        double dz = x * y - (8.0 / 3.0) * z;
        x += dt * dx; y += dt * dy; z += dt * dz;
        double al = 1.0 + 0.5 * z;
        double ha_n = ha + dt * (al * (hb - ha) + 0.2 * ha);
        double hb_n = hb + dt * (0.2 * (ha - hb));
        double ga_n = ga + dt * (al * (gb + c - ga) + 0.2 * ga);
        double gb_n = gb + dt * (al * c + 0.2 * (ga - gb));
        double c_n  = c - dt * ((al + 0.2) * c);
        ha = ha_n; hb = hb_n; ga = ga_n; gb = gb_n; c = c_n;
        T.ha[t] = (float)ha; T.ga[t] = (float)ga;
        T.hb[t] = (float)hb; T.gb[t] = (float)gb;
        T.cc[t] = (float)c;  T.zz[t] = (float)z;
    }
    return T;
}

__device__ constexpr Tabs G = make_tabs();

__device__ float g_pP[RBLK], g_pQ[RBLK];
__device__ int   g_done;                // reducers finished (self-resetting)
__device__ int   g_exit;                // blocks finished (self-resetting)
__device__ int   g_tile = WRITERS;      // next stealable tile (self-resetting)

__device__ __forceinline__ int load_acquire(const int* p) {
    int v;
    asm volatile("ld.acquire.gpu.global.s32 %0, [%1];" : "=r"(v) : "l"(p) : "memory");
    return v;
}

__global__ __launch_bounds__(NT)
void clf_fused(const float* __restrict__ vL,
               const float* __restrict__ vJ,
               float* __restrict__ out)
{
    const int bid = blockIdx.x;
    const float4* vL4 = (const float4*)vL;
    const float4* vJ4 = (const float4*)vJ;

    // ---- phase 0: blocks 0..63 produce P,Q partials ----
    if (bid < RBLK) {
        int k = bid * NT + threadIdx.x;       // 1024 floats per block
        float4 l = vL4[k];
        float4 j = vJ4[k];
        float p = l.x * l.x + l.y * l.y + l.z * l.z + l.w * l.w;
        float q = l.x * j.x + l.y * j.y + l.z * j.z + l.w * j.w;

        #pragma unroll
        for (int off = 16; off > 0; off >>= 1) {
            p += __shfl_down_sync(0xffffffffu, p, off);
            q += __shfl_down_sync(0xffffffffu, q, off);
        }
        __shared__ float sp[8], sq[8];
        int wid = threadIdx.x >> 5, lid = threadIdx.x & 31;
        if (lid == 0) { sp[wid] = p; sq[wid] = q; }
        __syncthreads();
        if (threadIdx.x == 0) {
            float P = 0.0f, Q = 0.0f;
            #pragma unroll
            for (int i = 0; i < 8; i++) { P += sp[i]; Q += sq[i]; }
            g_pP[bid] = P;
            g_pQ[bid] = Q;
            __threadfence();                   // publish partials
            atomicAdd(&g_done, 1);
        }
    }

    // block RBLK (a non-reducer) emits traj_z so it doesn't serialize
    // behind reducer duty.
    if (bid == RBLK) {
        float* out_z = out + 2ull * STEPS * DIM;
        for (int i = threadIdx.x; i < STEPS; i += NT)
            out_z[i] = G.zz[i];
    }

    // ---- register prefetch of static first tile, overlapping the wait ----
    int slice0 = bid & (NSLICE - 1);
    int f_pre  = slice0 * (NT * 2) + threadIdx.x;
    float4 pl0 = __ldg(vL4 + f_pre);
    float4 pj0 = __ldg(vJ4 + f_pre);
    float4 pl1 = __ldg(vL4 + f_pre + NT);
    float4 pj1 = __ldg(vJ4 + f_pre + NT);

    // ---- one-time wait for all partials ----
    if (threadIdx.x == 0) {
        while (load_acquire(&g_done) < RBLK)
            __nanosleep(64);
    }
    __syncthreads();

    // ---- evaluate closed form into smem ----
    float P = 0.0f, Q = 0.0f;
    #pragma unroll 16
    for (int i = 0; i < RBLK; i++) { P += g_pP[i]; Q += g_pQ[i]; }
    const float Kq = Q / P;

    __shared__ float sa[STEPS], sb[STEPS], sc[STEPS];
    for (int i = threadIdx.x; i < STEPS; i += NT) {
        sa[i] = fmaf(Kq, G.ga[i], G.ha[i]);
        sb[i] = fmaf(Kq, G.gb[i], G.hb[i]);
        sc[i] = G.cc[i];
    }
    __syncthreads();

    // ---- streaming stores (2 float4/thread) with work stealing ----
    float4* outL4 = (float4*)out;
    float4* outJ4 = outL4 + (size_t)STEPS * (DIM / 4);

    __shared__ int s_tt;
    int tt = bid;                             // static first tile (prefetched)
    while (tt < NTILES) {
        int chunk = tt >> 5;                  // NSLICE = 32
        int slice = tt & (NSLICE - 1);
        int f0    = slice * (NT * 2) + threadIdx.x;
        int t0    = chunk * CHUNK;

        float4 l0, j0, l1, j1;
        if (tt == bid) { l0 = pl0; j0 = pj0; l1 = pl1; j1 = pj1; }
        else {
            l0 = __ldg(vL4 + f0);
            j0 = __ldg(vJ4 + f0);
            l1 = __ldg(vL4 + f0 + NT);
            j1 = __ldg(vJ4 + f0 + NT);
        }

        float4* pL = outL4 + (size_t)t0 * (DIM / 4) + f0;
        float4* pJ = outJ4 + (size_t)t0 * (DIM / 4) + f0;

        #pragma unroll
        for (int u = 0; u < CHUNK; u++) {
            float a = sa[t0 + u], b = sb[t0 + u], c = sc[t0 + u];

            float4 oL0 = make_float4(a * l0.x, a * l0.y, a * l0.z, a * l0.w);
            float4 oL1 = make_float4(a * l1.x, a * l1.y, a * l1.z, a * l1.w);
            float4 oJ0 = make_float4(fmaf(b, l0.x, c * j0.x),
                                     fmaf(b, l0.y, c * j0.y),
                                     fmaf(b, l0.z, c * j0.z),
                                     fmaf(b, l0.w, c * j0.w));
            float4 oJ1 = make_float4(fmaf(b, l1.x, c * j1.x),
                                     fmaf(b, l1.y, c * j1.y),
                                     fmaf(b, l1.z, c * j1.z),
                                     fmaf(b, l1.w, c * j1.w));

            __stcg(pL,      oL0);             // A/B vs __stcs: default L2 policy
            __stcg(pL + NT, oL1);
            __stcg(pJ,      oJ0);
            __stcg(pJ + NT, oJ1);
            pL += DIM / 4;
            pJ += DIM / 4;
        }

        if (threadIdx.x == 0)
            s_tt = atomicAdd(&g_tile, 1);     // steal next tile
        __syncthreads();
        tt = s_tt;
        __syncthreads();
    }

    // ---- self-reset for next graph replay ----
    if (threadIdx.x == 0) {
        int v = atomicAdd(&g_exit, 1);
        if (v == WRITERS - 1) {
            g_done = 0;
            g_exit = 0;
            g_tile = WRITERS;
            __threadfence();
        }
    }
}

extern "C" void kernel_launch(void* const* d_in, const int* in_sizes, int n_in,
                              void* d_out, int out_size)
{
    const float* vL = (const float*)d_in[0];
    const float* vJ = (const float*)d_in[1];
    float* out = (float*)d_out;

    clf_fused<<<WRITERS, NT>>>(vL, vJ, out);
}

// round 15
// speedup vs baseline: 1.0815x; 1.0815x over previous
#include <cuda_runtime.h>
#include <cstdint>

// CognitiveLorenzField, closed form, single fused kernel.
// a_t = ha[t]+Kq*ga[t], b_t = hb[t]+Kq*gb[t], c_t = cc[t]; tables + Lorenz z
// computed at compile time in double. Runtime = dot-product reduction (blocks
// 0..63) + pure streaming stores at the DRAM-write wall (~5.5 TB/s).
// R15: A/B fewer write streams — 296 CTAs (2/SM) on the R12 winner
// (__stcs restored, 2 float4/thread, 8KB tiles, work stealing).

#define DIM       65536
#define STEPS     500
#define NSLICE    32                    // slices of 2048 floats (8KB)
#define TCHUNKS   50
#define CHUNK     10
#define NTILES    (TCHUNKS * NSLICE)    // 1600
#define NT        256
#define WRITERS   296                   // 2 CTA/SM, one wave
#define RBLK      64

struct Tabs {
    float ha[STEPS], ga[STEPS], hb[STEPS], gb[STEPS], cc[STEPS], zz[STEPS];
};

static constexpr Tabs make_tabs() {
    Tabs T{};
    double x = 1.0, y = 1.0, z = 1.0;
    double ha = 1.0, hb = 0.0, ga = 0.0, gb = 0.0, c = 1.0;
    const double dt = 0.01;
    for (int t = 0; t < STEPS; t++) {
        double dx = 10.0 * (y - x);
        double dy = x * (28.0 - z) - y;
        double dz = x * y - (8.0 / 3.0) * z;
        x += dt * dx; y += dt * dy; z += dt * dz;
        double al = 1.0 + 0.5 * z;
        double ha_n = ha + dt * (al * (hb - ha) + 0.2 * ha);
        double hb_n = hb + dt * (0.2 * (ha - hb));
        double ga_n = ga + dt * (al * (gb + c - ga) + 0.2 * ga);
        double gb_n = gb + dt * (al * c + 0.2 * (ga - gb));
        double c_n  = c - dt * ((al + 0.2) * c);
        ha = ha_n; hb = hb_n; ga = ga_n; gb = gb_n; c = c_n;
        T.ha[t] = (float)ha; T.ga[t] = (float)ga;
        T.hb[t] = (float)hb; T.gb[t] = (float)gb;
        T.cc[t] = (float)c;  T.zz[t] = (float)z;
    }
    return T;
}

__device__ constexpr Tabs G = make_tabs();

__device__ float g_pP[RBLK], g_pQ[RBLK];
__device__ int   g_done;                // reducers finished (self-resetting)
__device__ int   g_exit;                // blocks finished (self-resetting)
__device__ int   g_tile = WRITERS;      // next stealable tile (self-resetting)

__device__ __forceinline__ int load_acquire(const int* p) {
    int v;
    asm volatile("ld.acquire.gpu.global.s32 %0, [%1];" : "=r"(v) : "l"(p) : "memory");
    return v;
}

__global__ __launch_bounds__(NT)
void clf_fused(const float* __restrict__ vL,
               const float* __restrict__ vJ,
               float* __restrict__ out)
{
    const int bid = blockIdx.x;
    const float4* vL4 = (const float4*)vL;
    const float4* vJ4 = (const float4*)vJ;

    // ---- phase 0: blocks 0..63 produce P,Q partials ----
    if (bid < RBLK) {
        int k = bid * NT + threadIdx.x;       // 1024 floats per block
        float4 l = vL4[k];
        float4 j = vJ4[k];
        float p = l.x * l.x + l.y * l.y + l.z * l.z + l.w * l.w;
        float q = l.x * j.x + l.y * j.y + l.z * j.z + l.w * j.w;

        #pragma unroll
        for (int off = 16; off > 0; off >>= 1) {
            p += __shfl_down_sync(0xffffffffu, p, off);
            q += __shfl_down_sync(0xffffffffu, q, off);
        }
        __shared__ float sp[8], sq[8];
        int wid = threadIdx.x >> 5, lid = threadIdx.x & 31;
        if (lid == 0) { sp[wid] = p; sq[wid] = q; }
        __syncthreads();
        if (threadIdx.x == 0) {
            float P = 0.0f, Q = 0.0f;
            #pragma unroll
            for (int i = 0; i < 8; i++) { P += sp[i]; Q += sq[i]; }
            g_pP[bid] = P;
            g_pQ[bid] = Q;
            __threadfence();                   // publish partials
            atomicAdd(&g_done, 1);
        }
    }

    // a non-reducer block emits traj_z (input-independent)
    if (bid == RBLK) {
        float* out_z = out + 2ull * STEPS * DIM;
        for (int i = threadIdx.x; i < STEPS; i += NT)
            out_z[i] = G.zz[i];
    }

    // ---- register prefetch of static first tile, overlapping the wait ----
    int slice0 = bid & (NSLICE - 1);
    int f_pre  = slice0 * (NT * 2) + threadIdx.x;
    float4 pl0 = __ldg(vL4 + f_pre);
    float4 pj0 = __ldg(vJ4 + f_pre);
    float4 pl1 = __ldg(vL4 + f_pre + NT);
    float4 pj1 = __ldg(vJ4 + f_pre + NT);

    // ---- one-time wait for all partials ----
    if (threadIdx.x == 0) {
        while (load_acquire(&g_done) < RBLK)
            __nanosleep(64);
    }
    __syncthreads();

    // ---- evaluate closed form into smem ----
    float P = 0.0f, Q = 0.0f;
    #pragma unroll 16
    for (int i = 0; i < RBLK; i++) { P += g_pP[i]; Q += g_pQ[i]; }
    const float Kq = Q / P;

    __shared__ float sa[STEPS], sb[STEPS], sc[STEPS];
    for (int i = threadIdx.x; i < STEPS; i += NT) {
        sa[i] = fmaf(Kq, G.ga[i], G.ha[i]);
        sb[i] = fmaf(Kq, G.gb[i], G.hb[i]);
        sc[i] = G.cc[i];
    }
    __syncthreads();

    // ---- streaming stores (2 float4/thread) with work stealing ----
    float4* outL4 = (float4*)out;
    float4* outJ4 = outL4 + (size_t)STEPS * (DIM / 4);

    __shared__ int s_tt;
    int tt = bid;                             // static first tile (prefetched)
    while (tt < NTILES) {
        int chunk = tt >> 5;                  // NSLICE = 32
        int slice = tt & (NSLICE - 1);
        int f0    = slice * (NT * 2) + threadIdx.x;
        int t0    = chunk * CHUNK;

        float4 l0, j0, l1, j1;
        if (tt == bid) { l0 = pl0; j0 = pj0; l1 = pl1; j1 = pj1; }
        else {
            l0 = __ldg(vL4 + f0);
            j0 = __ldg(vJ4 + f0);
            l1 = __ldg(vL4 + f0 + NT);
            j1 = __ldg(vJ4 + f0 + NT);
        }

        float4* pL = outL4 + (size_t)t0 * (DIM / 4) + f0;
        float4* pJ = outJ4 + (size_t)t0 * (DIM / 4) + f0;

        #pragma unroll
        for (int u = 0; u < CHUNK; u++) {
            float a = sa[t0 + u], b = sb[t0 + u], c = sc[t0 + u];

            float4 oL0 = make_float4(a * l0.x, a * l0.y, a * l0.z, a * l0.w);
            float4 oL1 = make_float4(a * l1.x, a * l1.y, a * l1.z, a * l1.w);
            float4 oJ0 = make_float4(fmaf(b, l0.x, c * j0.x),
                                     fmaf(b, l0.y, c * j0.y),
                                     fmaf(b, l0.z, c * j0.z),
                                     fmaf(b, l0.w, c * j0.w));
            float4 oJ1 = make_float4(fmaf(b, l1.x, c * j1.x),
                                     fmaf(b, l1.y, c * j1.y),
                                     fmaf(b, l1.z, c * j1.z),
                                     fmaf(b, l1.w, c * j1.w));

            __stcs(pL,      oL0);
            __stcs(pL + NT, oL1);
            __stcs(pJ,      oJ0);
            __stcs(pJ + NT, oJ1);
            pL += DIM / 4;
            pJ += DIM / 4;
        }

        if (threadIdx.x == 0)
            s_tt = atomicAdd(&g_tile, 1);     // steal next tile
        __syncthreads();
        tt = s_tt;
        __syncthreads();
    }

    // ---- self-reset for next graph replay ----
    if (threadIdx.x == 0) {
        int v = atomicAdd(&g_exit, 1);
        if (v == WRITERS - 1) {
            g_done = 0;
            g_exit = 0;
            g_tile = WRITERS;
            __threadfence();
        }
    }
}

extern "C" void kernel_launch(void* const* d_in, const int* in_sizes, int n_in,
                              void* d_out, int out_size)
{
    const float* vL = (const float*)d_in[0];
    const float* vJ = (const float*)d_in[1];
    float* out = (float*)d_out;

    clf_fused<<<WRITERS, NT>>>(vL, vJ, out);
}

// round 16
// speedup vs baseline: 1.0822x; 1.0007x over previous
#include <cuda_runtime.h>
#include <cstdint>

// CognitiveLorenzField, closed form, single fused kernel.
// a_t = ha[t]+Kq*ga[t], b_t = hb[t]+Kq*gb[t], c_t = cc[t]; tables + Lorenz z
// computed at compile time in double. Runtime = dot-product reduction (blocks
// 0..63) + pure streaming stores at the DRAM-write wall.
// R16: continue the fewer-write-streams trend — 148 CTAs (1/SM).
// (1184 -> 4.20 TB/s, 592 -> 4.57, 296 -> 4.58 + smaller drain tail.)

#define DIM       65536
#define STEPS     500
#define NSLICE    32                    // slices of 2048 floats (8KB)
#define TCHUNKS   50
#define CHUNK     10
#define NTILES    (TCHUNKS * NSLICE)    // 1600
#define NT        256
#define WRITERS   148                   // 1 CTA/SM, one wave
#define RBLK      64

struct Tabs {
    float ha[STEPS], ga[STEPS], hb[STEPS], gb[STEPS], cc[STEPS], zz[STEPS];
};

static constexpr Tabs make_tabs() {
    Tabs T{};
    double x = 1.0, y = 1.0, z = 1.0;
    double ha = 1.0, hb = 0.0, ga = 0.0, gb = 0.0, c = 1.0;
    const double dt = 0.01;
    for (int t = 0; t < STEPS; t++) {
        double dx = 10.0 * (y - x);
        double dy = x * (28.0 - z) - y;
        double dz = x * y - (8.0 / 3.0) * z;
        x += dt * dx; y += dt * dy; z += dt * dz;
        double al = 1.0 + 0.5 * z;
        double ha_n = ha + dt * (al * (hb - ha) + 0.2 * ha);
        double hb_n = hb + dt * (0.2 * (ha - hb));
        double ga_n = ga + dt * (al * (gb + c - ga) + 0.2 * ga);
        double gb_n = gb + dt * (al * c + 0.2 * (ga - gb));
        double c_n  = c - dt * ((al + 0.2) * c);
        ha = ha_n; hb = hb_n; ga = ga_n; gb = gb_n; c = c_n;
        T.ha[t] = (float)ha; T.ga[t] = (float)ga;
        T.hb[t] = (float)hb; T.gb[t] = (float)gb;
        T.cc[t] = (float)c;  T.zz[t] = (float)z;
    }
    return T;
}

__device__ constexpr Tabs G = make_tabs();

__device__ float g_pP[RBLK], g_pQ[RBLK];
__device__ int   g_done;                // reducers finished (self-resetting)
__device__ int   g_exit;                // blocks finished (self-resetting)
__device__ int   g_tile = WRITERS;      // next stealable tile (self-resetting)

__device__ __forceinline__ int load_acquire(const int* p) {
    int v;
    asm volatile("ld.acquire.gpu.global.s32 %0, [%1];" : "=r"(v) : "l"(p) : "memory");
    return v;
}

__global__ __launch_bounds__(NT)
void clf_fused(const float* __restrict__ vL,
               const float* __restrict__ vJ,
               float* __restrict__ out)
{
    const int bid = blockIdx.x;
    const float4* vL4 = (const float4*)vL;
    const float4* vJ4 = (const float4*)vJ;

    // ---- phase 0: blocks 0..63 produce P,Q partials ----
    if (bid < RBLK) {
        int k = bid * NT + threadIdx.x;       // 1024 floats per block
        float4 l = vL4[k];
        float4 j = vJ4[k];
        float p = l.x * l.x + l.y * l.y + l.z * l.z + l.w * l.w;
        float q = l.x * j.x + l.y * j.y + l.z * j.z + l.w * j.w;

        #pragma unroll
        for (int off = 16; off > 0; off >>= 1) {
            p += __shfl_down_sync(0xffffffffu, p, off);
            q += __shfl_down_sync(0xffffffffu, q, off);
        }
        __shared__ float sp[8], sq[8];
        int wid = threadIdx.x >> 5, lid = threadIdx.x & 31;
        if (lid == 0) { sp[wid] = p; sq[wid] = q; }
        __syncthreads();
        if (threadIdx.x == 0) {
            float P = 0.0f, Q = 0.0f;
            #pragma unroll
            for (int i = 0; i < 8; i++) { P += sp[i]; Q += sq[i]; }
            g_pP[bid] = P;
            g_pQ[bid] = Q;
            __threadfence();                   // publish partials
            atomicAdd(&g_done, 1);
        }
    }

    // a non-reducer block emits traj_z (input-independent)
    if (bid == RBLK) {
        float* out_z = out + 2ull * STEPS * DIM;
        for (int i = threadIdx.x; i < STEPS; i += NT)
            out_z[i] = G.zz[i];
    }

    // ---- register prefetch of static first tile, overlapping the wait ----
    int slice0 = bid & (NSLICE - 1);
    int f_pre  = slice0 * (NT * 2) + threadIdx.x;
    float4 pl0 = __ldg(vL4 + f_pre);
    float4 pj0 = __ldg(vJ4 + f_pre);
    float4 pl1 = __ldg(vL4 + f_pre + NT);
    float4 pj1 = __ldg(vJ4 + f_pre + NT);

    // ---- one-time wait for all partials ----
    if (threadIdx.x == 0) {
        while (load_acquire(&g_done) < RBLK)
            __nanosleep(64);
    }
    __syncthreads();

    // ---- evaluate closed form into smem ----
    float P = 0.0f, Q = 0.0f;
    #pragma unroll 16
    for (int i = 0; i < RBLK; i++) { P += g_pP[i]; Q += g_pQ[i]; }
    const float Kq = Q / P;

    __shared__ float sa[STEPS], sb[STEPS], sc[STEPS];
    for (int i = threadIdx.x; i < STEPS; i += NT) {
        sa[i] = fmaf(Kq, G.ga[i], G.ha[i]);
        sb[i] = fmaf(Kq, G.gb[i], G.hb[i]);
        sc[i] = G.cc[i];
    }
    __syncthreads();

    // ---- streaming stores (2 float4/thread) with work stealing ----
    float4* outL4 = (float4*)out;
    float4* outJ4 = outL4 + (size_t)STEPS * (DIM / 4);

    __shared__ int s_tt;
    int tt = bid;                             // static first tile (prefetched)
    while (tt < NTILES) {
        int chunk = tt >> 5;                  // NSLICE = 32
        int slice = tt & (NSLICE - 1);
        int f0    = slice * (NT * 2) + threadIdx.x;
        int t0    = chunk * CHUNK;

        float4 l0, j0, l1, j1;
        if (tt == bid) { l0 = pl0; j0 = pj0; l1 = pl1; j1 = pj1; }
        else {
            l0 = __ldg(vL4 + f0);
            j0 = __ldg(vJ4 + f0);
            l1 = __ldg(vL4 + f0 + NT);
            j1 = __ldg(vJ4 + f0 + NT);
        }

        float4* pL = outL4 + (size_t)t0 * (DIM / 4) + f0;
        float4* pJ = outJ4 + (size_t)t0 * (DIM / 4) + f0;

        #pragma unroll
        for (int u = 0; u < CHUNK; u++) {
            float a = sa[t0 + u], b = sb[t0 + u], c = sc[t0 + u];

            float4 oL0 = make_float4(a * l0.x, a * l0.y, a * l0.z, a * l0.w);
            float4 oL1 = make_float4(a * l1.x, a * l1.y, a * l1.z, a * l1.w);
            float4 oJ0 = make_float4(fmaf(b, l0.x, c * j0.x),
                                     fmaf(b, l0.y, c * j0.y),
                                     fmaf(b, l0.z, c * j0.z),
                                     fmaf(b, l0.w, c * j0.w));
            float4 oJ1 = make_float4(fmaf(b, l1.x, c * j1.x),
                                     fmaf(b, l1.y, c * j1.y),
                                     fmaf(b, l1.z, c * j1.z),
                                     fmaf(b, l1.w, c * j1.w));

            __stcs(pL,      oL0);
            __stcs(pL + NT, oL1);
            __stcs(pJ,      oJ0);
            __stcs(pJ + NT, oJ1);
            pL += DIM / 4;
            pJ += DIM / 4;
        }

        if (threadIdx.x == 0)
            s_tt = atomicAdd(&g_tile, 1);     // steal next tile
        __syncthreads();
        tt = s_tt;
        __syncthreads();
    }

    // ---- self-reset for next graph replay ----
    if (threadIdx.x == 0) {
        int v = atomicAdd(&g_exit, 1);
        if (v == WRITERS - 1) {
            g_done = 0;
            g_exit = 0;
            g_tile = WRITERS;
            __threadfence();
        }
    }
}

extern "C" void kernel_launch(void* const* d_in, const int* in_sizes, int n_in,
                              void* d_out, int out_size)
{
    const float* vL = (const float*)d_in[0];
    const float* vJ = (const float*)d_in[1];
    float* out = (float*)d_out;

    clf_fused<<<WRITERS, NT>>>(vL, vJ, out);
}